// round 14
// baseline (speedup 1.0000x reference)
#include <cuda_runtime.h>
#include <cuda_fp16.h>
#include <math.h>
#include <stdint.h>

#define BB 2
#define TT 2048
#define DD 2048
#define NHEADS 16
#define NKVH 8
#define HDIM 128

// Scratch (allocation-free rule: __device__ globals)
static __device__ __half g_qh[(size_t)BB * NHEADS * TT * HDIM]; // Q fp16 (roped, scaled)
static __device__ __half g_kh[(size_t)BB * NKVH * TT * HDIM];   // K fp16 (roped)
static __device__ __half g_vh[(size_t)BB * NKVH * TT * HDIM];   // V fp16
static __device__ float2 g_tab[(size_t)BB * TT * 64];           // rope cos/sin
static __device__ __half g_xh[(size_t)4096 * 2048];             // x fp16
static __device__ __half g_wth[(size_t)4096 * 2048];            // [q;kv] weights^T fp16
static __device__ __half g_woth[(size_t)2048 * 2048];           // w_out^T fp16
static __device__ __half g_ench[(size_t)4096 * 2048];           // encoded fp16

// ---------------------------------------------------------------------------
// helpers
// ---------------------------------------------------------------------------
__device__ __forceinline__ uint32_t smem_u32(const void* p) {
    return (uint32_t)__cvta_generic_to_shared(p);
}
__device__ __forceinline__ void ldm4(uint32_t* r, uint32_t addr) {
    asm volatile("ldmatrix.sync.aligned.m8n8.x4.shared.b16 {%0,%1,%2,%3}, [%4];"
                 : "=r"(r[0]), "=r"(r[1]), "=r"(r[2]), "=r"(r[3]) : "r"(addr));
}
__device__ __forceinline__ void ldm4t(uint32_t* r, uint32_t addr) {
    asm volatile("ldmatrix.sync.aligned.m8n8.x4.trans.shared.b16 {%0,%1,%2,%3}, [%4];"
                 : "=r"(r[0]), "=r"(r[1]), "=r"(r[2]), "=r"(r[3]) : "r"(addr));
}
__device__ __forceinline__ void mma_f16(float* d, const uint32_t* a, const uint32_t* b) {
    asm volatile(
        "mma.sync.aligned.m16n8k16.row.col.f32.f16.f16.f32 "
        "{%0,%1,%2,%3}, {%4,%5,%6,%7}, {%8,%9}, {%0,%1,%2,%3};"
        : "+f"(d[0]), "+f"(d[1]), "+f"(d[2]), "+f"(d[3])
        : "r"(a[0]), "r"(a[1]), "r"(a[2]), "r"(a[3]), "r"(b[0]), "r"(b[1]));
}
__device__ __forceinline__ void cpa16(uint32_t dst, const void* src) {
    asm volatile("cp.async.cg.shared.global [%0], [%1], 16;"
                 :: "r"(dst), "l"(src) : "memory");
}
__device__ __forceinline__ void cpa_commit() {
    asm volatile("cp.async.commit_group;" ::: "memory");
}
template <int N> __device__ __forceinline__ void cpa_wait() {
    asm volatile("cp.async.wait_group %0;" :: "n"(N) : "memory");
}
__device__ __forceinline__ uint32_t pack_h2(float a, float b) {
    __half2 h = __floats2half2_rn(a, b);
    return *(uint32_t*)&h;
}

// ---------------------------------------------------------------------------
// fp16 GEMM: 128x128 tile, BK=32 halfs, 4-stage cp.async, 256 thr (8 warps,
// 4x2), warp tile 32x64, mma m16n8k16 f32 accum. A [M][K], Bt [N][K] fp16.
// MODE 0: per-head epilogue -> rope+fp16 Q/K, fp16 V. MODE 1: fp32 Cout.
// ---------------------------------------------------------------------------
#define HLD 40
#define H_STG (128 * HLD)
#define NHS 4
#define HSMEM (NHS * 2 * H_STG * 2)  // 81920 B
#define SLD 132                      // fp32 staging row stride (epilogue)

template <int MODE>
__global__ __launch_bounds__(256, 2) void gemm_h(
    const __half* __restrict__ A, const __half* __restrict__ Bt,
    float* __restrict__ Cout)
{
    extern __shared__ __half smh[];
    __half* As = smh;
    __half* Bs = smh + NHS * H_STG;
    const int tid = threadIdx.x;
    const int lane = tid & 31, warp = tid >> 5;
    const int m_warp = (warp & 3) * 32, n_warp = (warp >> 2) * 64;
    const int n0 = blockIdx.x * 128, m0 = blockIdx.y * 128;
    const int K = 2048;

    const int lrow = tid >> 2, lseg = tid & 3;
    const __half* pA = A + (size_t)(m0 + lrow) * K + lseg * 8;
    const __half* pA2 = pA + (size_t)64 * K;
    const __half* pB = Bt + (size_t)(n0 + lrow) * K + lseg * 8;
    const __half* pB2 = pB + (size_t)64 * K;
    const uint32_t sd1 = (uint32_t)(lrow * HLD + lseg * 8) * 2u;
    const uint32_t sd2 = (uint32_t)((lrow + 64) * HLD + lseg * 8) * 2u;
    const uint32_t aBase = smem_u32(As), bBase = smem_u32(Bs);

    const uint32_t aoff =
        (uint32_t)((m_warp + (lane & 15)) * HLD + (lane >> 4) * 8) * 2u;
    const uint32_t boff =
        (uint32_t)((n_warp + (lane >> 4) * 8 + (lane & 7)) * HLD +
                   ((lane >> 3) & 1) * 8) * 2u;

    float acc[2][8][4];
#pragma unroll
    for (int mt = 0; mt < 2; mt++)
#pragma unroll
        for (int nt = 0; nt < 8; nt++)
#pragma unroll
            for (int e = 0; e < 4; e++) acc[mt][nt][e] = 0.0f;

    const int NC = K / 32;

#pragma unroll
    for (int p = 0; p < NHS - 1; p++) {
        uint32_t ab = aBase + (uint32_t)(p * H_STG) * 2u;
        uint32_t bb = bBase + (uint32_t)(p * H_STG) * 2u;
        cpa16(ab + sd1, pA + p * 32);
        cpa16(ab + sd2, pA2 + p * 32);
        cpa16(bb + sd1, pB + p * 32);
        cpa16(bb + sd2, pB2 + p * 32);
        cpa_commit();
    }

    for (int c = 0; c < NC; c++) {
        const int s = c & (NHS - 1);
        cpa_wait<NHS - 2>();
        __syncthreads();
        const int cn = c + NHS - 1;
        if (cn < NC) {
            const int sn = cn & (NHS - 1);
            uint32_t ab = aBase + (uint32_t)(sn * H_STG) * 2u;
            uint32_t bb = bBase + (uint32_t)(sn * H_STG) * 2u;
            cpa16(ab + sd1, pA + cn * 32);
            cpa16(ab + sd2, pA2 + cn * 32);
            cpa16(bb + sd1, pB + cn * 32);
            cpa16(bb + sd2, pB2 + cn * 32);
        }
        cpa_commit();

        const uint32_t aSt = aBase + (uint32_t)(s * H_STG) * 2u + aoff;
        const uint32_t bSt = bBase + (uint32_t)(s * H_STG) * 2u + boff;
#pragma unroll
        for (int kb = 0; kb < 2; kb++) {
            uint32_t af[2][4];
            ldm4(af[0], aSt + (uint32_t)kb * 32u);
            ldm4(af[1], aSt + (uint32_t)(16 * HLD * 2) + (uint32_t)kb * 32u);
#pragma unroll
            for (int g = 0; g < 4; g++) {
                uint32_t bf[4];
                ldm4(bf, bSt + (uint32_t)(g * 16 * HLD * 2) + (uint32_t)kb * 32u);
#pragma unroll
                for (int mt = 0; mt < 2; mt++) {
                    mma_f16(acc[mt][2 * g + 0], af[mt], bf + 0);
                    mma_f16(acc[mt][2 * g + 1], af[mt], bf + 2);
                }
            }
        }
    }

    // epilogue
    const int r = lane >> 2, cq = (lane & 3) * 2;
    const int headn = n0 >> 7;  // whole 128-col block = one head
    if (MODE == 1) {
#pragma unroll
        for (int mt = 0; mt < 2; mt++) {
            const int row0 = m0 + m_warp + mt * 16 + r;
            const int row1 = row0 + 8;
            float* d0 = Cout + (size_t)row0 * 2048 + n0 + n_warp + cq;
            float* d1 = Cout + (size_t)row1 * 2048 + n0 + n_warp + cq;
#pragma unroll
            for (int nt = 0; nt < 8; nt++) {
                *(float2*)(d0 + nt * 8) = make_float2(acc[mt][nt][0], acc[mt][nt][1]);
                *(float2*)(d1 + nt * 8) = make_float2(acc[mt][nt][2], acc[mt][nt][3]);
            }
        }
    } else if (headn >= 24) {  // V -> fp16 directly
#pragma unroll
        for (int mt = 0; mt < 2; mt++) {
            const int row0 = m0 + m_warp + mt * 16 + r;
            const int row1 = row0 + 8;
            __half* base = g_vh + ((size_t)((row0 >> 11) * 8 + headn - 24)) * TT * HDIM;
            __half* d0 = base + (size_t)(row0 & 2047) * HDIM + n_warp + cq;
            __half* d1 = base + (size_t)(row1 & 2047) * HDIM + n_warp + cq;
#pragma unroll
            for (int nt = 0; nt < 8; nt++) {
                *(__half2*)(d0 + nt * 8) = __floats2half2_rn(acc[mt][nt][0], acc[mt][nt][1]);
                *(__half2*)(d1 + nt * 8) = __floats2half2_rn(acc[mt][nt][2], acc[mt][nt][3]);
            }
        }
    } else {  // Q or K: stage fp32 tile -> rope -> fp16
        float* st = (float*)smh;  // 128 x SLD fp32 = 67.6 KB (fits in 80 KB)
        __syncthreads();          // mainloop smem reads done
#pragma unroll
        for (int mt = 0; mt < 2; mt++) {
            const int lr0 = m_warp + mt * 16 + r;
#pragma unroll
            for (int nt = 0; nt < 8; nt++) {
                const int col = n_warp + nt * 8 + cq;
                *(float2*)&st[lr0 * SLD + col] = make_float2(acc[mt][nt][0], acc[mt][nt][1]);
                *(float2*)&st[(lr0 + 8) * SLD + col] = make_float2(acc[mt][nt][2], acc[mt][nt][3]);
            }
        }
        __syncthreads();
        const int r2 = tid >> 1, sg = tid & 1;  // 2 threads per row
        const int grow = m0 + r2;
        const int b = grow >> 11, t = grow & 2047;
        const bool isQ = headn < 16;
        const float scale = isQ ? 0.08838834764831845f : 1.0f;
        __half* dst = isQ
            ? g_qh + ((size_t)(b * NHEADS + headn) * TT + t) * HDIM
            : g_kh + ((size_t)(b * NKVH + headn - 16) * TT + t) * HDIM;
        const float2* tab = g_tab + ((size_t)b * TT + t) * 64;
        const float* row = st + r2 * SLD;
#pragma unroll
        for (int i = sg * 32; i < sg * 32 + 32; i += 2) {
            float2 cs0 = tab[i], cs1 = tab[i + 1];
            float a0 = row[i], b0 = row[i + 64];
            float a1 = row[i + 1], b1 = row[i + 65];
            *(__half2*)(dst + i) = __floats2half2_rn(
                (a0 * cs0.x - b0 * cs0.y) * scale, (a1 * cs1.x - b1 * cs1.y) * scale);
            *(__half2*)(dst + i + 64) = __floats2half2_rn(
                (b0 * cs0.x + a0 * cs0.y) * scale, (b1 * cs1.x + a1 * cs1.y) * scale);
        }
    }
}

// ---------------------------------------------------------------------------
// prep: fp16 convert-copy (x) + fp16 transposes (weights -> [N][K])
// ---------------------------------------------------------------------------
__global__ void conv_half(const float* __restrict__ src, __half* __restrict__ dst)
{
    int i = blockIdx.x * 256 + threadIdx.x;
    float4 v = ((const float4*)src)[i];
    ((__half2*)dst)[i * 2] = __floats2half2_rn(v.x, v.y);
    ((__half2*)dst)[i * 2 + 1] = __floats2half2_rn(v.z, v.w);
}

__global__ void transpose_half(const float* __restrict__ src, __half* __restrict__ dst,
                               int R, int C)
{
    __shared__ float tsm[32][33];
    const int p = blockIdx.z;
    src += (size_t)p * R * C;
    dst += (size_t)p * (size_t)C * 2048;
    int c0 = blockIdx.x * 32, r0 = blockIdx.y * 32;
#pragma unroll
    for (int j = threadIdx.y; j < 32; j += 8)
        tsm[j][threadIdx.x] = src[(size_t)(r0 + j) * C + c0 + threadIdx.x];
    __syncthreads();
#pragma unroll
    for (int j = threadIdx.y; j < 32; j += 8)
        dst[(size_t)(c0 + j) * 2048 + r0 + threadIdx.x] = __float2half_rn(tsm[threadIdx.x][j]);
}

// ---------------------------------------------------------------------------
// RoPE table
// ---------------------------------------------------------------------------
struct TsTab { double ts[64]; };

__global__ void rope_table(const int* __restrict__ pos, TsTab tt)
{
    int idx = blockIdx.x * blockDim.x + threadIdx.x;
    int i = idx & 63;
    int t = (idx >> 6) & (TT - 1);
    int b = idx >> 17;
    double th = (double)pos[b * TT + t] * tt.ts[i];
    double sd, cd;
    sincos(th, &sd, &cd);
    g_tab[idx] = make_float2((float)cd, (float)sd);
}

// ---------------------------------------------------------------------------
// MUFU-free softcap + exp
// ---------------------------------------------------------------------------
__device__ __forceinline__ float softcap(float x) {
    float y = x * 0.02f;
    float u = y * y;
    float pl = fmaf(u, -0.00886324f, 0.02186949f);
    pl = fmaf(u, pl, -0.05396825f);
    pl = fmaf(u, pl, 0.13333333f);
    pl = fmaf(u, pl, -0.33333333f);
    pl = fmaf(u, pl, 1.0f);
    float cap = x * pl;
    if (fabsf(y) > 0.58f) {
        float t = __expf(2.0f * fabsf(y));
        float th = 1.0f - __fdividef(2.0f, t + 1.0f);
        cap = copysignf(50.0f * th, x);
    }
    return cap;
}
__device__ __forceinline__ float expfast(float a) {
    float t = a * 1.442695041f;
    float rr = t + 12582912.0f;
    float nf = rr - 12582912.0f;
    float f = t - nf;
    float e = fmaf(f, 1.5403530e-4f, 1.3333558e-3f);
    e = fmaf(f, e, 9.6181291e-3f);
    e = fmaf(f, e, 5.5504109e-2f);
    e = fmaf(f, e, 2.4022651e-1f);
    e = fmaf(f, e, 6.9314718e-1f);
    e = fmaf(f, e, 1.0f);
    int ni = (__float_as_int(rr) & 0x7FFFFF) - 0x400000;
    return e * __int_as_float((ni + 127) << 23);
}

// ---------------------------------------------------------------------------
// fp16 flash attention: 128 q-rows/block (8 warps x 16), KV tiles 64,
// cp.async double-buffered fp16 K/V, online softmax with rescale-skip,
// register-resident P (S frag layout == PV A-frag layout).
// ---------------------------------------------------------------------------
#define KVLD 136
#define STG_H (64 * KVLD)            // 8704 halfs per operand/stage
#define SMEM_ATTN (4 * STG_H * 2)    // 69632 B

__global__ __launch_bounds__(256, 1) void attn_kernel()
{
    extern __shared__ __half smh[];
    __half* Qs = smh;  // alias over stage buffers (pre-loop only)

    const int tid = threadIdx.x;
    const int lane = tid & 31, warp = tid >> 5;
    const int wm = warp * 16;
    const int lr = lane >> 2, lc = (lane & 3) * 2;
    const int qi = (TT / 128 - 1) - blockIdx.x;  // heavy blocks first
    const int q0 = qi * 128;
    const int n = blockIdx.y, b = blockIdx.z;
    const int kvh = n >> 1;
    const __half* Qp = g_qh + ((size_t)(b * NHEADS + n)) * TT * HDIM;
    const __half* Kp = g_kh + ((size_t)(b * NKVH + kvh)) * TT * HDIM;
    const __half* Vp = g_vh + ((size_t)(b * NKVH + kvh)) * TT * HDIM;

    // ---- Q tile (128x128 fp16) -> smem -> persistent fragments
#pragma unroll
    for (int p = 0; p < 8; p++) {
        int idx = tid + p * 256;
        int r = idx >> 4, sg = idx & 15;
        cpa16(smem_u32(Qs + r * KVLD + sg * 8), Qp + (size_t)(q0 + r) * HDIM + sg * 8);
    }
    cpa_commit();
    cpa_wait<0>();
    __syncthreads();
    uint32_t qf[8][4];
    {
        uint32_t baseQ = smem_u32(Qs) +
            (uint32_t)((wm + (lane & 15)) * KVLD + (lane >> 4) * 8) * 2u;
#pragma unroll
        for (int kb = 0; kb < 8; kb++) ldm4(qf[kb], baseQ + (uint32_t)kb * 32u);
    }
    __syncthreads();

    float o[16][4];
#pragma unroll
    for (int nt = 0; nt < 16; nt++)
#pragma unroll
        for (int e = 0; e < 4; e++) o[nt][e] = 0.0f;
    float ls0 = 0.0f, ls1 = 0.0f, m0 = -1e30f, m1 = -1e30f;

    const int gr0 = q0 + wm + lr;
    const int gr1 = gr0 + 8;

    const int ntiles = 2 * qi + 2;

    // prologue: tile 0 -> stage 0
    {
#pragma unroll
        for (int p = 0; p < 4; p++) {
            int idx = tid + p * 256;
            int r = idx >> 4, sg = idx & 15;
            uint32_t off = (uint32_t)(r * KVLD + sg * 8) * 2u;
            cpa16(smem_u32(smh) + off, Kp + (size_t)r * HDIM + sg * 8);
            cpa16(smem_u32(smh) + (uint32_t)STG_H * 2u + off,
                  Vp + (size_t)r * HDIM + sg * 8);
        }
        cpa_commit();
    }

    for (int t = 0; t < ntiles; t++) {
        const int s = t & 1;
        const uint32_t stBase = smem_u32(smh) + (uint32_t)(s * 2 * STG_H) * 2u;
        cpa_wait<0>();
        __syncthreads();
        // prefetch tile t+1 into other stage
        if (t + 1 < ntiles) {
            const uint32_t nb = smem_u32(smh) + (uint32_t)(((t + 1) & 1) * 2 * STG_H) * 2u;
            const size_t g0 = (size_t)(t + 1) * 64;
#pragma unroll
            for (int p = 0; p < 4; p++) {
                int idx = tid + p * 256;
                int r = idx >> 4, sg = idx & 15;
                uint32_t off = (uint32_t)(r * KVLD + sg * 8) * 2u;
                cpa16(nb + off, Kp + (g0 + r) * HDIM + sg * 8);
                cpa16(nb + (uint32_t)STG_H * 2u + off, Vp + (g0 + r) * HDIM + sg * 8);
            }
            cpa_commit();
        }

        const int s0 = t * 64;
        // S = Q K^T (per warp: 16 rows x 64 cols)
        const uint32_t kBase = stBase +
            (uint32_t)(((lane >> 4) * 8 + (lane & 7)) * KVLD + ((lane >> 3) & 1) * 8) * 2u;
        float sa[8][4];
#pragma unroll
        for (int nt = 0; nt < 8; nt++)
#pragma unroll
            for (int e = 0; e < 4; e++) sa[nt][e] = 0.0f;
#pragma unroll
        for (int kb = 0; kb < 8; kb++) {
#pragma unroll
            for (int g = 0; g < 4; g++) {
                uint32_t bf[4];
                ldm4(bf, kBase + (uint32_t)(g * 16 * KVLD * 2) + (uint32_t)kb * 32u);
                mma_f16(sa[2 * g + 0], qf[kb], bf + 0);
                mma_f16(sa[2 * g + 1], qf[kb], bf + 2);
            }
        }

        // softcap + causal mask + online max
        float tm0 = -1e30f, tm1 = -1e30f;
#pragma unroll
        for (int nt = 0; nt < 8; nt++) {
            int c = s0 + nt * 8 + lc;
            sa[nt][0] = softcap(sa[nt][0]);
            sa[nt][1] = softcap(sa[nt][1]);
            sa[nt][2] = softcap(sa[nt][2]);
            sa[nt][3] = softcap(sa[nt][3]);
            tm0 = fmaxf(tm0, fmaxf(c <= gr0 ? sa[nt][0] : -1e30f,
                                   c + 1 <= gr0 ? sa[nt][1] : -1e30f));
            tm1 = fmaxf(tm1, fmaxf(c <= gr1 ? sa[nt][2] : -1e30f,
                                   c + 1 <= gr1 ? sa[nt][3] : -1e30f));
        }
        tm0 = fmaxf(tm0, __shfl_xor_sync(0xffffffffu, tm0, 1));
        tm0 = fmaxf(tm0, __shfl_xor_sync(0xffffffffu, tm0, 2));
        tm1 = fmaxf(tm1, __shfl_xor_sync(0xffffffffu, tm1, 1));
        tm1 = fmaxf(tm1, __shfl_xor_sync(0xffffffffu, tm1, 2));
        float mn0 = fmaxf(m0, tm0), mn1 = fmaxf(m1, tm1);
        // rescale only when the running max actually changed (warp-uniform)
        if (__any_sync(0xffffffffu, (mn0 > m0) || (mn1 > m1))) {
            float a0 = expfast(fmaxf(m0 - mn0, -80.0f));
            float a1 = expfast(fmaxf(m1 - mn1, -80.0f));
            m0 = mn0; m1 = mn1;
            ls0 *= a0; ls1 *= a1;
#pragma unroll
            for (int nt = 0; nt < 16; nt++) {
                o[nt][0] *= a0; o[nt][1] *= a0;
                o[nt][2] *= a1; o[nt][3] *= a1;
            }
        }
        // exp -> register-resident P (packed half2, A-fragment layout)
        uint32_t ph[8][2];
#pragma unroll
        for (int nt = 0; nt < 8; nt++) {
            int c = s0 + nt * 8 + lc;
            float p0 = (c <= gr0) ? expfast(fmaxf(sa[nt][0] - m0, -80.0f)) : 0.0f;
            float p1 = (c + 1 <= gr0) ? expfast(fmaxf(sa[nt][1] - m0, -80.0f)) : 0.0f;
            float p2 = (c <= gr1) ? expfast(fmaxf(sa[nt][2] - m1, -80.0f)) : 0.0f;
            float p3 = (c + 1 <= gr1) ? expfast(fmaxf(sa[nt][3] - m1, -80.0f)) : 0.0f;
            ls0 += p0 + p1;
            ls1 += p2 + p3;
            ph[nt][0] = pack_h2(p0, p1);
            ph[nt][1] = pack_h2(p2, p3);
        }

        // O += P V (per warp: 16 rows x 128 cols), P from registers
        const uint32_t vBase = stBase + (uint32_t)STG_H * 2u +
            (uint32_t)((lane & 15) * KVLD + (lane >> 4) * 8) * 2u;
#pragma unroll
        for (int kb = 0; kb < 4; kb++) {
            const uint32_t pf[4] = {ph[2 * kb][0], ph[2 * kb][1],
                                    ph[2 * kb + 1][0], ph[2 * kb + 1][1]};
            const uint32_t vSt = vBase + (uint32_t)(kb * 16 * KVLD * 2);
#pragma unroll
            for (int j = 0; j < 8; j++) {
                uint32_t vf[4];
                ldm4t(vf, vSt + (uint32_t)(j * 16) * 2u);
                mma_f16(o[2 * j + 0], pf, vf + 0);
                mma_f16(o[2 * j + 1], pf, vf + 2);
            }
        }
        __syncthreads();  // all warps done reading stage s before overwrite
    }

    // finalize
    ls0 += __shfl_xor_sync(0xffffffffu, ls0, 1);
    ls0 += __shfl_xor_sync(0xffffffffu, ls0, 2);
    ls1 += __shfl_xor_sync(0xffffffffu, ls1, 1);
    ls1 += __shfl_xor_sync(0xffffffffu, ls1, 2);
    float i0 = 1.0f / ls0, i1 = 1.0f / ls1;
    __half* er0 = g_ench + ((size_t)(b * TT + gr0)) * 2048 + n * HDIM + lc;
    __half* er1 = g_ench + ((size_t)(b * TT + gr1)) * 2048 + n * HDIM + lc;
#pragma unroll
    for (int nt = 0; nt < 16; nt++) {
        *(__half2*)(er0 + nt * 8) = __floats2half2_rn(o[nt][0] * i0, o[nt][1] * i0);
        *(__half2*)(er1 + nt * 8) = __floats2half2_rn(o[nt][2] * i1, o[nt][3] * i1);
    }
}

// ---------------------------------------------------------------------------
extern "C" void kernel_launch(void* const* d_in, const int* in_sizes, int n_in,
                              void* d_out, int out_size)
{
    const float* x = (const float*)d_in[0];
    const int* positions = (const int*)d_in[1];
    // d_in[2] = attn_mask (causal) — analytic
    const float* w_q = (const float*)d_in[3];
    const float* w_kv = (const float*)d_in[4];
    const float* w_out = (const float*)d_in[5];
    float* out = (float*)d_out;

    __half *xh, *wth, *woth, *ench;
    cudaGetSymbolAddress((void**)&xh, g_xh);
    cudaGetSymbolAddress((void**)&wth, g_wth);
    cudaGetSymbolAddress((void**)&woth, g_woth);
    cudaGetSymbolAddress((void**)&ench, g_ench);

    TsTab tt;
    for (int i = 0; i < 64; i++) tt.ts[i] = pow(10000.0, -(double)i / 64.0);

    // prep (rope table first: proj epilogue consumes it)
    rope_table<<<(BB * TT * 64) / 256, 256>>>(positions, tt);
    conv_half<<<(BB * TT * DD) / 1024, 256>>>(x, xh);
    transpose_half<<<dim3(4, 64, 16), dim3(32, 8)>>>(w_q, wth, 2048, 128);
    transpose_half<<<dim3(4, 64, 16), dim3(32, 8)>>>(
        w_kv, wth + (size_t)2048 * 2048, 2048, 128);
    transpose_half<<<dim3(64, 64, 1), dim3(32, 8)>>>(w_out, woth, 2048, 2048);

    // merged QKV projection with fused rope epilogue
    cudaFuncSetAttribute(gemm_h<0>, cudaFuncAttributeMaxDynamicSharedMemorySize,
                         HSMEM);
    cudaFuncSetAttribute(gemm_h<1>, cudaFuncAttributeMaxDynamicSharedMemorySize,
                         HSMEM);
    gemm_h<0><<<dim3(32, 32), 256, HSMEM>>>(xh, wth, nullptr);

    cudaFuncSetAttribute(attn_kernel, cudaFuncAttributeMaxDynamicSharedMemorySize,
                         SMEM_ATTN);
    attn_kernel<<<dim3(TT / 128, NHEADS, BB), 256, SMEM_ATTN>>>();

    // output projection
    gemm_h<1><<<dim3(16, 32), 256, HSMEM>>>(ench, woth, out);
}

// round 15
// speedup vs baseline: 1.0003x; 1.0003x over previous
#include <cuda_runtime.h>
#include <cuda_fp16.h>
#include <math.h>
#include <stdint.h>

#define BB 2
#define TT 2048
#define DD 2048
#define NHEADS 16
#define NKVH 8
#define HDIM 128

// Scratch (allocation-free rule: __device__ globals)
static __device__ __half g_qh[(size_t)BB * NHEADS * TT * HDIM]; // Q fp16 (roped, scaled)
static __device__ __half g_kh[(size_t)BB * NKVH * TT * HDIM];   // K fp16 (roped)
static __device__ __half g_vh[(size_t)BB * NKVH * TT * HDIM];   // V fp16
static __device__ float2 g_tab[(size_t)BB * TT * 64];           // rope cos/sin
static __device__ __half g_xh[(size_t)4096 * 2048];             // x fp16
static __device__ __half g_wth[(size_t)4096 * 2048];            // [q;kv] weights^T fp16
static __device__ __half g_woth[(size_t)2048 * 2048];           // w_out^T fp16
static __device__ __half g_ench[(size_t)4096 * 2048];           // encoded fp16

// ---------------------------------------------------------------------------
// helpers
// ---------------------------------------------------------------------------
__device__ __forceinline__ uint32_t smem_u32(const void* p) {
    return (uint32_t)__cvta_generic_to_shared(p);
}
__device__ __forceinline__ void ldm4(uint32_t* r, uint32_t addr) {
    asm volatile("ldmatrix.sync.aligned.m8n8.x4.shared.b16 {%0,%1,%2,%3}, [%4];"
                 : "=r"(r[0]), "=r"(r[1]), "=r"(r[2]), "=r"(r[3]) : "r"(addr));
}
__device__ __forceinline__ void ldm4t(uint32_t* r, uint32_t addr) {
    asm volatile("ldmatrix.sync.aligned.m8n8.x4.trans.shared.b16 {%0,%1,%2,%3}, [%4];"
                 : "=r"(r[0]), "=r"(r[1]), "=r"(r[2]), "=r"(r[3]) : "r"(addr));
}
__device__ __forceinline__ void mma_f16(float* d, const uint32_t* a, const uint32_t* b) {
    asm volatile(
        "mma.sync.aligned.m16n8k16.row.col.f32.f16.f16.f32 "
        "{%0,%1,%2,%3}, {%4,%5,%6,%7}, {%8,%9}, {%0,%1,%2,%3};"
        : "+f"(d[0]), "+f"(d[1]), "+f"(d[2]), "+f"(d[3])
        : "r"(a[0]), "r"(a[1]), "r"(a[2]), "r"(a[3]), "r"(b[0]), "r"(b[1]));
}
__device__ __forceinline__ void cpa16(uint32_t dst, const void* src) {
    asm volatile("cp.async.cg.shared.global [%0], [%1], 16;"
                 :: "r"(dst), "l"(src) : "memory");
}
__device__ __forceinline__ void cpa_commit() {
    asm volatile("cp.async.commit_group;" ::: "memory");
}
template <int N> __device__ __forceinline__ void cpa_wait() {
    asm volatile("cp.async.wait_group %0;" :: "n"(N) : "memory");
}
__device__ __forceinline__ uint32_t pack_h2(float a, float b) {
    __half2 h = __floats2half2_rn(a, b);
    return *(uint32_t*)&h;
}

// ---------------------------------------------------------------------------
// fp16 GEMM: 128x128 tile, BK=32 halfs, 4-stage cp.async, 256 thr (8 warps,
// 4x2), warp tile 32x64, mma m16n8k16 f32 accum. A [M][K], Bt [N][K] fp16.
// MODE 0: per-head epilogue -> rope+fp16 Q/K, fp16 V. MODE 1: fp32 Cout.
// ---------------------------------------------------------------------------
#define HLD 40
#define H_STG (128 * HLD)
#define NHS 4
#define HSMEM (NHS * 2 * H_STG * 2)  // 81920 B
#define SLD 132                      // fp32 staging row stride (epilogue)

template <int MODE>
__global__ __launch_bounds__(256, 2) void gemm_h(
    const __half* __restrict__ A, const __half* __restrict__ Bt,
    float* __restrict__ Cout)
{
    extern __shared__ __half smh[];
    __half* As = smh;
    __half* Bs = smh + NHS * H_STG;
    const int tid = threadIdx.x;
    const int lane = tid & 31, warp = tid >> 5;
    const int m_warp = (warp & 3) * 32, n_warp = (warp >> 2) * 64;
    const int n0 = blockIdx.x * 128, m0 = blockIdx.y * 128;
    const int K = 2048;

    const int lrow = tid >> 2, lseg = tid & 3;
    const __half* pA = A + (size_t)(m0 + lrow) * K + lseg * 8;
    const __half* pA2 = pA + (size_t)64 * K;
    const __half* pB = Bt + (size_t)(n0 + lrow) * K + lseg * 8;
    const __half* pB2 = pB + (size_t)64 * K;
    const uint32_t sd1 = (uint32_t)(lrow * HLD + lseg * 8) * 2u;
    const uint32_t sd2 = (uint32_t)((lrow + 64) * HLD + lseg * 8) * 2u;
    const uint32_t aBase = smem_u32(As), bBase = smem_u32(Bs);

    const uint32_t aoff =
        (uint32_t)((m_warp + (lane & 15)) * HLD + (lane >> 4) * 8) * 2u;
    const uint32_t boff =
        (uint32_t)((n_warp + (lane >> 4) * 8 + (lane & 7)) * HLD +
                   ((lane >> 3) & 1) * 8) * 2u;

    float acc[2][8][4];
#pragma unroll
    for (int mt = 0; mt < 2; mt++)
#pragma unroll
        for (int nt = 0; nt < 8; nt++)
#pragma unroll
            for (int e = 0; e < 4; e++) acc[mt][nt][e] = 0.0f;

    const int NC = K / 32;

#pragma unroll
    for (int p = 0; p < NHS - 1; p++) {
        uint32_t ab = aBase + (uint32_t)(p * H_STG) * 2u;
        uint32_t bb = bBase + (uint32_t)(p * H_STG) * 2u;
        cpa16(ab + sd1, pA + p * 32);
        cpa16(ab + sd2, pA2 + p * 32);
        cpa16(bb + sd1, pB + p * 32);
        cpa16(bb + sd2, pB2 + p * 32);
        cpa_commit();
    }

    for (int c = 0; c < NC; c++) {
        const int s = c & (NHS - 1);
        cpa_wait<NHS - 2>();
        __syncthreads();
        const int cn = c + NHS - 1;
        if (cn < NC) {
            const int sn = cn & (NHS - 1);
            uint32_t ab = aBase + (uint32_t)(sn * H_STG) * 2u;
            uint32_t bb = bBase + (uint32_t)(sn * H_STG) * 2u;
            cpa16(ab + sd1, pA + cn * 32);
            cpa16(ab + sd2, pA2 + cn * 32);
            cpa16(bb + sd1, pB + cn * 32);
            cpa16(bb + sd2, pB2 + cn * 32);
        }
        cpa_commit();

        const uint32_t aSt = aBase + (uint32_t)(s * H_STG) * 2u + aoff;
        const uint32_t bSt = bBase + (uint32_t)(s * H_STG) * 2u + boff;
#pragma unroll
        for (int kb = 0; kb < 2; kb++) {
            uint32_t af[2][4];
            ldm4(af[0], aSt + (uint32_t)kb * 32u);
            ldm4(af[1], aSt + (uint32_t)(16 * HLD * 2) + (uint32_t)kb * 32u);
#pragma unroll
            for (int g = 0; g < 4; g++) {
                uint32_t bf[4];
                ldm4(bf, bSt + (uint32_t)(g * 16 * HLD * 2) + (uint32_t)kb * 32u);
#pragma unroll
                for (int mt = 0; mt < 2; mt++) {
                    mma_f16(acc[mt][2 * g + 0], af[mt], bf + 0);
                    mma_f16(acc[mt][2 * g + 1], af[mt], bf + 2);
                }
            }
        }
    }

    // epilogue
    const int r = lane >> 2, cq = (lane & 3) * 2;
    const int headn = n0 >> 7;  // whole 128-col block = one head
    if (MODE == 1) {
#pragma unroll
        for (int mt = 0; mt < 2; mt++) {
            const int row0 = m0 + m_warp + mt * 16 + r;
            const int row1 = row0 + 8;
            float* d0 = Cout + (size_t)row0 * 2048 + n0 + n_warp + cq;
            float* d1 = Cout + (size_t)row1 * 2048 + n0 + n_warp + cq;
#pragma unroll
            for (int nt = 0; nt < 8; nt++) {
                *(float2*)(d0 + nt * 8) = make_float2(acc[mt][nt][0], acc[mt][nt][1]);
                *(float2*)(d1 + nt * 8) = make_float2(acc[mt][nt][2], acc[mt][nt][3]);
            }
        }
    } else if (headn >= 24) {  // V -> fp16 directly
#pragma unroll
        for (int mt = 0; mt < 2; mt++) {
            const int row0 = m0 + m_warp + mt * 16 + r;
            const int row1 = row0 + 8;
            __half* base = g_vh + ((size_t)((row0 >> 11) * 8 + headn - 24)) * TT * HDIM;
            __half* d0 = base + (size_t)(row0 & 2047) * HDIM + n_warp + cq;
            __half* d1 = base + (size_t)(row1 & 2047) * HDIM + n_warp + cq;
#pragma unroll
            for (int nt = 0; nt < 8; nt++) {
                *(__half2*)(d0 + nt * 8) = __floats2half2_rn(acc[mt][nt][0], acc[mt][nt][1]);
                *(__half2*)(d1 + nt * 8) = __floats2half2_rn(acc[mt][nt][2], acc[mt][nt][3]);
            }
        }
    } else {  // Q or K: stage fp32 tile -> rope -> fp16
        float* st = (float*)smh;  // 128 x SLD fp32 = 67.6 KB (fits in 80 KB)
        __syncthreads();          // mainloop smem reads done
#pragma unroll
        for (int mt = 0; mt < 2; mt++) {
            const int lr0 = m_warp + mt * 16 + r;
#pragma unroll
            for (int nt = 0; nt < 8; nt++) {
                const int col = n_warp + nt * 8 + cq;
                *(float2*)&st[lr0 * SLD + col] = make_float2(acc[mt][nt][0], acc[mt][nt][1]);
                *(float2*)&st[(lr0 + 8) * SLD + col] = make_float2(acc[mt][nt][2], acc[mt][nt][3]);
            }
        }
        __syncthreads();
        const int r2 = tid >> 1, sg = tid & 1;  // 2 threads per row
        const int grow = m0 + r2;
        const int b = grow >> 11, t = grow & 2047;
        const bool isQ = headn < 16;
        const float scale = isQ ? 0.08838834764831845f : 1.0f;
        __half* dst = isQ
            ? g_qh + ((size_t)(b * NHEADS + headn) * TT + t) * HDIM
            : g_kh + ((size_t)(b * NKVH + headn - 16) * TT + t) * HDIM;
        const float2* tab = g_tab + ((size_t)b * TT + t) * 64;
        const float* row = st + r2 * SLD;
#pragma unroll
        for (int i = sg * 32; i < sg * 32 + 32; i += 2) {
            float2 cs0 = tab[i], cs1 = tab[i + 1];
            float a0 = row[i], b0 = row[i + 64];
            float a1 = row[i + 1], b1 = row[i + 65];
            *(__half2*)(dst + i) = __floats2half2_rn(
                (a0 * cs0.x - b0 * cs0.y) * scale, (a1 * cs1.x - b1 * cs1.y) * scale);
            *(__half2*)(dst + i + 64) = __floats2half2_rn(
                (b0 * cs0.x + a0 * cs0.y) * scale, (b1 * cs1.x + a1 * cs1.y) * scale);
        }
    }
}

// ---------------------------------------------------------------------------
// prep: fp16 convert-copy (x) + fp16 transposes (weights -> [N][K])
// ---------------------------------------------------------------------------
__global__ void conv_half(const float* __restrict__ src, __half* __restrict__ dst)
{
    int i = blockIdx.x * 256 + threadIdx.x;
    float4 v = ((const float4*)src)[i];
    ((__half2*)dst)[i * 2] = __floats2half2_rn(v.x, v.y);
    ((__half2*)dst)[i * 2 + 1] = __floats2half2_rn(v.z, v.w);
}

__global__ void transpose_half(const float* __restrict__ src, __half* __restrict__ dst,
                               int R, int C)
{
    __shared__ float tsm[32][33];
    const int p = blockIdx.z;
    src += (size_t)p * R * C;
    dst += (size_t)p * (size_t)C * 2048;
    int c0 = blockIdx.x * 32, r0 = blockIdx.y * 32;
#pragma unroll
    for (int j = threadIdx.y; j < 32; j += 8)
        tsm[j][threadIdx.x] = src[(size_t)(r0 + j) * C + c0 + threadIdx.x];
    __syncthreads();
#pragma unroll
    for (int j = threadIdx.y; j < 32; j += 8)
        dst[(size_t)(c0 + j) * 2048 + r0 + threadIdx.x] = __float2half_rn(tsm[threadIdx.x][j]);
}

// ---------------------------------------------------------------------------
// RoPE table
// ---------------------------------------------------------------------------
struct TsTab { double ts[64]; };

__global__ void rope_table(const int* __restrict__ pos, TsTab tt)
{
    int idx = blockIdx.x * blockDim.x + threadIdx.x;
    int i = idx & 63;
    int t = (idx >> 6) & (TT - 1);
    int b = idx >> 17;
    double th = (double)pos[b * TT + t] * tt.ts[i];
    double sd, cd;
    sincos(th, &sd, &cd);
    g_tab[idx] = make_float2((float)cd, (float)sd);
}

// ---------------------------------------------------------------------------
// MUFU-free softcap + exp
// ---------------------------------------------------------------------------
__device__ __forceinline__ float softcap(float x) {
    float y = x * 0.02f;
    float u = y * y;
    float pl = fmaf(u, -0.00886324f, 0.02186949f);
    pl = fmaf(u, pl, -0.05396825f);
    pl = fmaf(u, pl, 0.13333333f);
    pl = fmaf(u, pl, -0.33333333f);
    pl = fmaf(u, pl, 1.0f);
    float cap = x * pl;
    if (fabsf(y) > 0.58f) {
        float t = __expf(2.0f * fabsf(y));
        float th = 1.0f - __fdividef(2.0f, t + 1.0f);
        cap = copysignf(50.0f * th, x);
    }
    return cap;
}
__device__ __forceinline__ float expfast(float a) {
    float t = a * 1.442695041f;
    float rr = t + 12582912.0f;
    float nf = rr - 12582912.0f;
    float f = t - nf;
    float e = fmaf(f, 1.5403530e-4f, 1.3333558e-3f);
    e = fmaf(f, e, 9.6181291e-3f);
    e = fmaf(f, e, 5.5504109e-2f);
    e = fmaf(f, e, 2.4022651e-1f);
    e = fmaf(f, e, 6.9314718e-1f);
    e = fmaf(f, e, 1.0f);
    int ni = (__float_as_int(rr) & 0x7FFFFF) - 0x400000;
    return e * __int_as_float((ni + 127) << 23);
}

// ---------------------------------------------------------------------------
// fp16 flash attention: 128 q-rows/block (8 warps x 16), KV tiles 64,
// cp.async double-buffered fp16 K/V, online softmax with rescale-skip,
// register-resident P (S frag layout == PV A-frag layout).
// ---------------------------------------------------------------------------
#define KVLD 136
#define STG_H (64 * KVLD)            // 8704 halfs per operand/stage
#define SMEM_ATTN (4 * STG_H * 2)    // 69632 B

__global__ __launch_bounds__(256, 1) void attn_kernel()
{
    extern __shared__ __half smh[];
    __half* Qs = smh;  // alias over stage buffers (pre-loop only)

    const int tid = threadIdx.x;
    const int lane = tid & 31, warp = tid >> 5;
    const int wm = warp * 16;
    const int lr = lane >> 2, lc = (lane & 3) * 2;
    const int qi = (TT / 128 - 1) - blockIdx.x;  // heavy blocks first
    const int q0 = qi * 128;
    const int n = blockIdx.y, b = blockIdx.z;
    const int kvh = n >> 1;
    const __half* Qp = g_qh + ((size_t)(b * NHEADS + n)) * TT * HDIM;
    const __half* Kp = g_kh + ((size_t)(b * NKVH + kvh)) * TT * HDIM;
    const __half* Vp = g_vh + ((size_t)(b * NKVH + kvh)) * TT * HDIM;

    // ---- Q tile (128x128 fp16) -> smem -> persistent fragments
#pragma unroll
    for (int p = 0; p < 8; p++) {
        int idx = tid + p * 256;
        int r = idx >> 4, sg = idx & 15;
        cpa16(smem_u32(Qs + r * KVLD + sg * 8), Qp + (size_t)(q0 + r) * HDIM + sg * 8);
    }
    cpa_commit();
    cpa_wait<0>();
    __syncthreads();
    uint32_t qf[8][4];
    {
        uint32_t baseQ = smem_u32(Qs) +
            (uint32_t)((wm + (lane & 15)) * KVLD + (lane >> 4) * 8) * 2u;
#pragma unroll
        for (int kb = 0; kb < 8; kb++) ldm4(qf[kb], baseQ + (uint32_t)kb * 32u);
    }
    __syncthreads();

    float o[16][4];
#pragma unroll
    for (int nt = 0; nt < 16; nt++)
#pragma unroll
        for (int e = 0; e < 4; e++) o[nt][e] = 0.0f;
    float ls0 = 0.0f, ls1 = 0.0f, m0 = -1e30f, m1 = -1e30f;

    const int gr0 = q0 + wm + lr;
    const int gr1 = gr0 + 8;

    const int ntiles = 2 * qi + 2;

    // prologue: tile 0 -> stage 0
    {
#pragma unroll
        for (int p = 0; p < 4; p++) {
            int idx = tid + p * 256;
            int r = idx >> 4, sg = idx & 15;
            uint32_t off = (uint32_t)(r * KVLD + sg * 8) * 2u;
            cpa16(smem_u32(smh) + off, Kp + (size_t)r * HDIM + sg * 8);
            cpa16(smem_u32(smh) + (uint32_t)STG_H * 2u + off,
                  Vp + (size_t)r * HDIM + sg * 8);
        }
        cpa_commit();
    }

    for (int t = 0; t < ntiles; t++) {
        const int s = t & 1;
        const uint32_t stBase = smem_u32(smh) + (uint32_t)(s * 2 * STG_H) * 2u;
        cpa_wait<0>();
        __syncthreads();
        // prefetch tile t+1 into other stage
        if (t + 1 < ntiles) {
            const uint32_t nb = smem_u32(smh) + (uint32_t)(((t + 1) & 1) * 2 * STG_H) * 2u;
            const size_t g0 = (size_t)(t + 1) * 64;
#pragma unroll
            for (int p = 0; p < 4; p++) {
                int idx = tid + p * 256;
                int r = idx >> 4, sg = idx & 15;
                uint32_t off = (uint32_t)(r * KVLD + sg * 8) * 2u;
                cpa16(nb + off, Kp + (g0 + r) * HDIM + sg * 8);
                cpa16(nb + (uint32_t)STG_H * 2u + off, Vp + (g0 + r) * HDIM + sg * 8);
            }
            cpa_commit();
        }

        const int s0 = t * 64;
        // S = Q K^T (per warp: 16 rows x 64 cols)
        const uint32_t kBase = stBase +
            (uint32_t)(((lane >> 4) * 8 + (lane & 7)) * KVLD + ((lane >> 3) & 1) * 8) * 2u;
        float sa[8][4];
#pragma unroll
        for (int nt = 0; nt < 8; nt++)
#pragma unroll
            for (int e = 0; e < 4; e++) sa[nt][e] = 0.0f;
#pragma unroll
        for (int kb = 0; kb < 8; kb++) {
#pragma unroll
            for (int g = 0; g < 4; g++) {
                uint32_t bf[4];
                ldm4(bf, kBase + (uint32_t)(g * 16 * KVLD * 2) + (uint32_t)kb * 32u);
                mma_f16(sa[2 * g + 0], qf[kb], bf + 0);
                mma_f16(sa[2 * g + 1], qf[kb], bf + 2);
            }
        }

        // softcap + causal mask + online max
        float tm0 = -1e30f, tm1 = -1e30f;
#pragma unroll
        for (int nt = 0; nt < 8; nt++) {
            int c = s0 + nt * 8 + lc;
            sa[nt][0] = softcap(sa[nt][0]);
            sa[nt][1] = softcap(sa[nt][1]);
            sa[nt][2] = softcap(sa[nt][2]);
            sa[nt][3] = softcap(sa[nt][3]);
            tm0 = fmaxf(tm0, fmaxf(c <= gr0 ? sa[nt][0] : -1e30f,
                                   c + 1 <= gr0 ? sa[nt][1] : -1e30f));
            tm1 = fmaxf(tm1, fmaxf(c <= gr1 ? sa[nt][2] : -1e30f,
                                   c + 1 <= gr1 ? sa[nt][3] : -1e30f));
        }
        tm0 = fmaxf(tm0, __shfl_xor_sync(0xffffffffu, tm0, 1));
        tm0 = fmaxf(tm0, __shfl_xor_sync(0xffffffffu, tm0, 2));
        tm1 = fmaxf(tm1, __shfl_xor_sync(0xffffffffu, tm1, 1));
        tm1 = fmaxf(tm1, __shfl_xor_sync(0xffffffffu, tm1, 2));
        float mn0 = fmaxf(m0, tm0), mn1 = fmaxf(m1, tm1);
        // rescale only when the running max actually changed (warp-uniform)
        if (__any_sync(0xffffffffu, (mn0 > m0) || (mn1 > m1))) {
            float a0 = expfast(fmaxf(m0 - mn0, -80.0f));
            float a1 = expfast(fmaxf(m1 - mn1, -80.0f));
            m0 = mn0; m1 = mn1;
            ls0 *= a0; ls1 *= a1;
#pragma unroll
            for (int nt = 0; nt < 16; nt++) {
                o[nt][0] *= a0; o[nt][1] *= a0;
                o[nt][2] *= a1; o[nt][3] *= a1;
            }
        }
        // exp -> register-resident P (packed half2, A-fragment layout)
        uint32_t ph[8][2];
#pragma unroll
        for (int nt = 0; nt < 8; nt++) {
            int c = s0 + nt * 8 + lc;
            float p0 = (c <= gr0) ? expfast(fmaxf(sa[nt][0] - m0, -80.0f)) : 0.0f;
            float p1 = (c + 1 <= gr0) ? expfast(fmaxf(sa[nt][1] - m0, -80.0f)) : 0.0f;
            float p2 = (c <= gr1) ? expfast(fmaxf(sa[nt][2] - m1, -80.0f)) : 0.0f;
            float p3 = (c + 1 <= gr1) ? expfast(fmaxf(sa[nt][3] - m1, -80.0f)) : 0.0f;
            ls0 += p0 + p1;
            ls1 += p2 + p3;
            ph[nt][0] = pack_h2(p0, p1);
            ph[nt][1] = pack_h2(p2, p3);
        }

        // O += P V (per warp: 16 rows x 128 cols), P from registers
        const uint32_t vBase = stBase + (uint32_t)STG_H * 2u +
            (uint32_t)((lane & 15) * KVLD + (lane >> 4) * 8) * 2u;
#pragma unroll
        for (int kb = 0; kb < 4; kb++) {
            const uint32_t pf[4] = {ph[2 * kb][0], ph[2 * kb][1],
                                    ph[2 * kb + 1][0], ph[2 * kb + 1][1]};
            const uint32_t vSt = vBase + (uint32_t)(kb * 16 * KVLD * 2);
#pragma unroll
            for (int j = 0; j < 8; j++) {
                uint32_t vf[4];
                ldm4t(vf, vSt + (uint32_t)(j * 16) * 2u);
                mma_f16(o[2 * j + 0], pf, vf + 0);
                mma_f16(o[2 * j + 1], pf, vf + 2);
            }
        }
        __syncthreads();  // all warps done reading stage s before overwrite
    }

    // finalize
    ls0 += __shfl_xor_sync(0xffffffffu, ls0, 1);
    ls0 += __shfl_xor_sync(0xffffffffu, ls0, 2);
    ls1 += __shfl_xor_sync(0xffffffffu, ls1, 1);
    ls1 += __shfl_xor_sync(0xffffffffu, ls1, 2);
    float i0 = 1.0f / ls0, i1 = 1.0f / ls1;
    __half* er0 = g_ench + ((size_t)(b * TT + gr0)) * 2048 + n * HDIM + lc;
    __half* er1 = g_ench + ((size_t)(b * TT + gr1)) * 2048 + n * HDIM + lc;
#pragma unroll
    for (int nt = 0; nt < 16; nt++) {
        *(__half2*)(er0 + nt * 8) = __floats2half2_rn(o[nt][0] * i0, o[nt][1] * i0);
        *(__half2*)(er1 + nt * 8) = __floats2half2_rn(o[nt][2] * i1, o[nt][3] * i1);
    }
}

// ---------------------------------------------------------------------------
extern "C" void kernel_launch(void* const* d_in, const int* in_sizes, int n_in,
                              void* d_out, int out_size)
{
    const float* x = (const float*)d_in[0];
    const int* positions = (const int*)d_in[1];
    // d_in[2] = attn_mask (causal) — analytic
    const float* w_q = (const float*)d_in[3];
    const float* w_kv = (const float*)d_in[4];
    const float* w_out = (const float*)d_in[5];
    float* out = (float*)d_out;

    __half *xh, *wth, *woth, *ench;
    cudaGetSymbolAddress((void**)&xh, g_xh);
    cudaGetSymbolAddress((void**)&wth, g_wth);
    cudaGetSymbolAddress((void**)&woth, g_woth);
    cudaGetSymbolAddress((void**)&ench, g_ench);

    TsTab tt;
    for (int i = 0; i < 64; i++) tt.ts[i] = pow(10000.0, -(double)i / 64.0);

    // prep (rope table first: proj epilogue consumes it)
    rope_table<<<(BB * TT * 64) / 256, 256>>>(positions, tt);
    conv_half<<<(BB * TT * DD) / 1024, 256>>>(x, xh);
    transpose_half<<<dim3(4, 64, 16), dim3(32, 8)>>>(w_q, wth, 2048, 128);
    transpose_half<<<dim3(4, 64, 16), dim3(32, 8)>>>(
        w_kv, wth + (size_t)2048 * 2048, 2048, 128);
    transpose_half<<<dim3(64, 64, 1), dim3(32, 8)>>>(w_out, woth, 2048, 2048);

    // merged QKV projection with fused rope epilogue
    cudaFuncSetAttribute(gemm_h<0>, cudaFuncAttributeMaxDynamicSharedMemorySize,
                         HSMEM);
    cudaFuncSetAttribute(gemm_h<1>, cudaFuncAttributeMaxDynamicSharedMemorySize,
                         HSMEM);
    gemm_h<0><<<dim3(32, 32), 256, HSMEM>>>(xh, wth, nullptr);

    cudaFuncSetAttribute(attn_kernel, cudaFuncAttributeMaxDynamicSharedMemorySize,
                         SMEM_ATTN);
    attn_kernel<<<dim3(TT / 128, NHEADS, BB), 256, SMEM_ATTN>>>();

    // output projection
    gemm_h<1><<<dim3(16, 32), 256, HSMEM>>>(ench, woth, out);
}

// round 16
// speedup vs baseline: 1.2051x; 1.2047x over previous
#include <cuda_runtime.h>
#include <cuda_fp16.h>
#include <math.h>
#include <stdint.h>

#define BB 2
#define TT 2048
#define DD 2048
#define NHEADS 16
#define NKVH 8
#define HDIM 128

// Scratch (allocation-free rule: __device__ globals)
static __device__ float g_qf[(size_t)BB * NHEADS * TT * HDIM];  // Q fp32 (rope input)
static __device__ float g_kf[(size_t)BB * NKVH * TT * HDIM];    // K fp32 (rope input)
static __device__ __half g_qh[(size_t)BB * NHEADS * TT * HDIM]; // Q fp16 (roped, scaled)
static __device__ __half g_kh[(size_t)BB * NKVH * TT * HDIM];   // K fp16 (roped)
static __device__ __half g_vh[(size_t)BB * NKVH * TT * HDIM];   // V fp16
static __device__ float2 g_tab[(size_t)BB * TT * 64];           // rope cos/sin
static __device__ __half g_xh[(size_t)4096 * 2048];             // x fp16
static __device__ __half g_wth[(size_t)4096 * 2048];            // [q;kv] weights^T fp16
static __device__ __half g_woth[(size_t)2048 * 2048];           // w_out^T fp16
static __device__ __half g_ench[(size_t)4096 * 2048];           // encoded fp16

// ---------------------------------------------------------------------------
// helpers
// ---------------------------------------------------------------------------
__device__ __forceinline__ uint32_t smem_u32(const void* p) {
    return (uint32_t)__cvta_generic_to_shared(p);
}
__device__ __forceinline__ void ldm4(uint32_t* r, uint32_t addr) {
    asm volatile("ldmatrix.sync.aligned.m8n8.x4.shared.b16 {%0,%1,%2,%3}, [%4];"
                 : "=r"(r[0]), "=r"(r[1]), "=r"(r[2]), "=r"(r[3]) : "r"(addr));
}
__device__ __forceinline__ void ldm4t(uint32_t* r, uint32_t addr) {
    asm volatile("ldmatrix.sync.aligned.m8n8.x4.trans.shared.b16 {%0,%1,%2,%3}, [%4];"
                 : "=r"(r[0]), "=r"(r[1]), "=r"(r[2]), "=r"(r[3]) : "r"(addr));
}
__device__ __forceinline__ void mma_f16(float* d, const uint32_t* a, const uint32_t* b) {
    asm volatile(
        "mma.sync.aligned.m16n8k16.row.col.f32.f16.f16.f32 "
        "{%0,%1,%2,%3}, {%4,%5,%6,%7}, {%8,%9}, {%0,%1,%2,%3};"
        : "+f"(d[0]), "+f"(d[1]), "+f"(d[2]), "+f"(d[3])
        : "r"(a[0]), "r"(a[1]), "r"(a[2]), "r"(a[3]), "r"(b[0]), "r"(b[1]));
}
__device__ __forceinline__ void cpa16(uint32_t dst, const void* src) {
    asm volatile("cp.async.cg.shared.global [%0], [%1], 16;"
                 :: "r"(dst), "l"(src) : "memory");
}
__device__ __forceinline__ void cpa_commit() {
    asm volatile("cp.async.commit_group;" ::: "memory");
}
template <int N> __device__ __forceinline__ void cpa_wait() {
    asm volatile("cp.async.wait_group %0;" :: "n"(N) : "memory");
}
__device__ __forceinline__ float ex2f(float x) {
    float r;
    asm("ex2.approx.f32 %0, %1;" : "=f"(r) : "f"(x));
    return r;
}

// ---------------------------------------------------------------------------
// fp16 GEMM: 128x128 tile, BK=32 halfs, 4-stage cp.async, 256 thr (8 warps,
// 4x2), warp tile 32x64, mma m16n8k16 f32 accum. A [M][K], Bt [N][K] fp16.
// MODE 0: scatter heads -> Q fp32 / K fp32 / V fp16. MODE 1: fp32 Cout.
// ---------------------------------------------------------------------------
#define HLD 40
#define H_STG (128 * HLD)
#define NHS 4
#define HSMEM (NHS * 2 * H_STG * 2)  // 81920 B

template <int MODE>
__global__ __launch_bounds__(256, 2) void gemm_h(
    const __half* __restrict__ A, const __half* __restrict__ Bt,
    float* __restrict__ Cout)
{
    extern __shared__ __half smh[];
    __half* As = smh;
    __half* Bs = smh + NHS * H_STG;
    const int tid = threadIdx.x;
    const int lane = tid & 31, warp = tid >> 5;
    const int m_warp = (warp & 3) * 32, n_warp = (warp >> 2) * 64;
    const int n0 = blockIdx.x * 128, m0 = blockIdx.y * 128;
    const int K = 2048;

    const int lrow = tid >> 2, lseg = tid & 3;
    const __half* pA = A + (size_t)(m0 + lrow) * K + lseg * 8;
    const __half* pA2 = pA + (size_t)64 * K;
    const __half* pB = Bt + (size_t)(n0 + lrow) * K + lseg * 8;
    const __half* pB2 = pB + (size_t)64 * K;
    const uint32_t sd1 = (uint32_t)(lrow * HLD + lseg * 8) * 2u;
    const uint32_t sd2 = (uint32_t)((lrow + 64) * HLD + lseg * 8) * 2u;
    const uint32_t aBase = smem_u32(As), bBase = smem_u32(Bs);

    const uint32_t aoff =
        (uint32_t)((m_warp + (lane & 15)) * HLD + (lane >> 4) * 8) * 2u;
    const uint32_t boff =
        (uint32_t)((n_warp + (lane >> 4) * 8 + (lane & 7)) * HLD +
                   ((lane >> 3) & 1) * 8) * 2u;

    float acc[2][8][4];
#pragma unroll
    for (int mt = 0; mt < 2; mt++)
#pragma unroll
        for (int nt = 0; nt < 8; nt++)
#pragma unroll
            for (int e = 0; e < 4; e++) acc[mt][nt][e] = 0.0f;

    const int NC = K / 32;

#pragma unroll
    for (int p = 0; p < NHS - 1; p++) {
        uint32_t ab = aBase + (uint32_t)(p * H_STG) * 2u;
        uint32_t bb = bBase + (uint32_t)(p * H_STG) * 2u;
        cpa16(ab + sd1, pA + p * 32);
        cpa16(ab + sd2, pA2 + p * 32);
        cpa16(bb + sd1, pB + p * 32);
        cpa16(bb + sd2, pB2 + p * 32);
        cpa_commit();
    }

    for (int c = 0; c < NC; c++) {
        const int s = c & (NHS - 1);
        cpa_wait<NHS - 2>();
        __syncthreads();
        const int cn = c + NHS - 1;
        if (cn < NC) {
            const int sn = cn & (NHS - 1);
            uint32_t ab = aBase + (uint32_t)(sn * H_STG) * 2u;
            uint32_t bb = bBase + (uint32_t)(sn * H_STG) * 2u;
            cpa16(ab + sd1, pA + cn * 32);
            cpa16(ab + sd2, pA2 + cn * 32);
            cpa16(bb + sd1, pB + cn * 32);
            cpa16(bb + sd2, pB2 + cn * 32);
        }
        cpa_commit();

        const uint32_t aSt = aBase + (uint32_t)(s * H_STG) * 2u + aoff;
        const uint32_t bSt = bBase + (uint32_t)(s * H_STG) * 2u + boff;
#pragma unroll
        for (int kb = 0; kb < 2; kb++) {
            uint32_t af[2][4];
            ldm4(af[0], aSt + (uint32_t)kb * 32u);
            ldm4(af[1], aSt + (uint32_t)(16 * HLD * 2) + (uint32_t)kb * 32u);
#pragma unroll
            for (int g = 0; g < 4; g++) {
                uint32_t bf[4];
                ldm4(bf, bSt + (uint32_t)(g * 16 * HLD * 2) + (uint32_t)kb * 32u);
#pragma unroll
                for (int mt = 0; mt < 2; mt++) {
                    mma_f16(acc[mt][2 * g + 0], af[mt], bf + 0);
                    mma_f16(acc[mt][2 * g + 1], af[mt], bf + 2);
                }
            }
        }
    }

    // epilogue
    const int r = lane >> 2, cq = (lane & 3) * 2;
    const int headn = (n0 + n_warp) >> 7;
    const int hb = (n0 + n_warp) & 127;
#pragma unroll
    for (int mt = 0; mt < 2; mt++) {
        const int row0 = m0 + m_warp + mt * 16 + r;
        const int row1 = row0 + 8;
        if (MODE == 1) {
            float* d0 = Cout + (size_t)row0 * 2048 + n0 + n_warp + cq;
            float* d1 = Cout + (size_t)row1 * 2048 + n0 + n_warp + cq;
#pragma unroll
            for (int nt = 0; nt < 8; nt++) {
                *(float2*)(d0 + nt * 8) = make_float2(acc[mt][nt][0], acc[mt][nt][1]);
                *(float2*)(d1 + nt * 8) = make_float2(acc[mt][nt][2], acc[mt][nt][3]);
            }
        } else if (headn < 24) {  // Q or K -> fp32 (rope input)
            float* base;
            if (headn < 16)
                base = g_qf + ((size_t)((row0 >> 11) * 16 + headn)) * TT * HDIM;
            else
                base = g_kf + ((size_t)((row0 >> 11) * 8 + headn - 16)) * TT * HDIM;
            float* d0 = base + (size_t)(row0 & 2047) * HDIM + hb + cq;
            float* d1 = base + (size_t)(row1 & 2047) * HDIM + hb + cq;
#pragma unroll
            for (int nt = 0; nt < 8; nt++) {
                *(float2*)(d0 + nt * 8) = make_float2(acc[mt][nt][0], acc[mt][nt][1]);
                *(float2*)(d1 + nt * 8) = make_float2(acc[mt][nt][2], acc[mt][nt][3]);
            }
        } else {  // V -> fp16 directly
            __half* base = g_vh + ((size_t)((row0 >> 11) * 8 + headn - 24)) * TT * HDIM;
            __half* d0 = base + (size_t)(row0 & 2047) * HDIM + hb + cq;
            __half* d1 = base + (size_t)(row1 & 2047) * HDIM + hb + cq;
#pragma unroll
            for (int nt = 0; nt < 8; nt++) {
                *(__half2*)(d0 + nt * 8) = __floats2half2_rn(acc[mt][nt][0], acc[mt][nt][1]);
                *(__half2*)(d1 + nt * 8) = __floats2half2_rn(acc[mt][nt][2], acc[mt][nt][3]);
            }
        }
    }
}

// ---------------------------------------------------------------------------
// prep: fp16 convert-copy (x) + fp16 transposes (weights -> [N][K])
// ---------------------------------------------------------------------------
__global__ void conv_half(const float* __restrict__ src, __half* __restrict__ dst)
{
    int i = blockIdx.x * 256 + threadIdx.x;
    float4 v = ((const float4*)src)[i];
    ((__half2*)dst)[i * 2] = __floats2half2_rn(v.x, v.y);
    ((__half2*)dst)[i * 2 + 1] = __floats2half2_rn(v.z, v.w);
}

__global__ void transpose_half(const float* __restrict__ src, __half* __restrict__ dst,
                               int R, int C)
{
    __shared__ float tsm[32][33];
    const int p = blockIdx.z;
    src += (size_t)p * R * C;
    dst += (size_t)p * (size_t)C * 2048;
    int c0 = blockIdx.x * 32, r0 = blockIdx.y * 32;
#pragma unroll
    for (int j = threadIdx.y; j < 32; j += 8)
        tsm[j][threadIdx.x] = src[(size_t)(r0 + j) * C + c0 + threadIdx.x];
    __syncthreads();
#pragma unroll
    for (int j = threadIdx.y; j < 32; j += 8)
        dst[(size_t)(c0 + j) * 2048 + r0 + threadIdx.x] = __float2half_rn(tsm[threadIdx.x][j]);
}

// ---------------------------------------------------------------------------
// RoPE: table + fused rope->fp16 apply (Q scaled)
// ---------------------------------------------------------------------------
struct TsTab { double ts[64]; };

__global__ void rope_table(const int* __restrict__ pos, TsTab tt)
{
    int idx = blockIdx.x * blockDim.x + threadIdx.x;
    int i = idx & 63;
    int t = (idx >> 6) & (TT - 1);
    int b = idx >> 17;
    double th = (double)pos[b * TT + t] * tt.ts[i];
    double sd, cd;
    sincos(th, &sd, &cd);
    g_tab[idx] = make_float2((float)cd, (float)sd);
}

__global__ void rope_to_half(const float* __restrict__ src, __half* __restrict__ dst,
                             int nheads, float scale)
{
    int idx = blockIdx.x * blockDim.x + threadIdx.x;
    int i = idx & 63;
    int t = (idx >> 6) & (TT - 1);
    int rest = idx >> 17;
    int hd = rest % nheads;
    int b = rest / nheads;
    if (b >= BB) return;
    float2 cs = g_tab[((size_t)b * TT + t) * 64 + i];
    size_t base = (((size_t)(b * nheads + hd)) * TT + t) * HDIM;
    float f = src[base + i];
    float se = src[base + 64 + i];
    dst[base + i] = __float2half_rn((f * cs.x - se * cs.y) * scale);
    dst[base + 64 + i] = __float2half_rn((se * cs.x + f * cs.y) * scale);
}

// ---------------------------------------------------------------------------
// fp16 flash attention: 128 q-rows/block (8 warps x 16), KV tiles 64,
// cp.async double-buffered fp16 K/V, online softmax (MUFU ex2, poly softcap
// with asymptote clamp, warp-uniform rescale-skip), 1 block sync / tile.
// ---------------------------------------------------------------------------
#define KVLD 136
#define PLD 72
#define STG_H (64 * KVLD)                         // 8704 halfs per operand/stage
#define SMEM_ATTN ((4 * STG_H + 128 * PLD) * 2)   // 88064 B
#define L2E 1.442695041f

__global__ __launch_bounds__(256, 1) void attn_kernel()
{
    extern __shared__ __half smh[];
    __half* Ps = smh + 4 * STG_H;
    __half* Qs = smh;  // alias over stage buffers (pre-loop only)

    const int tid = threadIdx.x;
    const int lane = tid & 31, warp = tid >> 5;
    const int wm = warp * 16;
    const int lr = lane >> 2, lc = (lane & 3) * 2;
    const int qi = (TT / 128 - 1) - blockIdx.x;  // heavy blocks first
    const int q0 = qi * 128;
    const int n = blockIdx.y, b = blockIdx.z;
    const int kvh = n >> 1;
    const __half* Qp = g_qh + ((size_t)(b * NHEADS + n)) * TT * HDIM;
    const __half* Kp = g_kh + ((size_t)(b * NKVH + kvh)) * TT * HDIM;
    const __half* Vp = g_vh + ((size_t)(b * NKVH + kvh)) * TT * HDIM;

    // ---- Q tile (128x128 fp16) -> smem -> persistent fragments
#pragma unroll
    for (int p = 0; p < 8; p++) {
        int idx = tid + p * 256;
        int r = idx >> 4, sg = idx & 15;
        cpa16(smem_u32(Qs + r * KVLD + sg * 8), Qp + (size_t)(q0 + r) * HDIM + sg * 8);
    }
    cpa_commit();
    cpa_wait<0>();
    __syncthreads();
    uint32_t qf[8][4];
    {
        uint32_t baseQ = smem_u32(Qs) +
            (uint32_t)((wm + (lane & 15)) * KVLD + (lane >> 4) * 8) * 2u;
#pragma unroll
        for (int kb = 0; kb < 8; kb++) ldm4(qf[kb], baseQ + (uint32_t)kb * 32u);
    }
    __syncthreads();

    float o[16][4];
#pragma unroll
    for (int nt = 0; nt < 16; nt++)
#pragma unroll
        for (int e = 0; e < 4; e++) o[nt][e] = 0.0f;
    float ls0 = 0.0f, ls1 = 0.0f, m0 = -1e30f, m1 = -1e30f;

    const int gr0 = q0 + wm + lr;
    const int gr1 = gr0 + 8;
    const uint32_t pBase = smem_u32(Ps) +
        (uint32_t)((wm + (lane & 15)) * PLD + (lane >> 4) * 8) * 2u;

    const int ntiles = 2 * qi + 2;

    // prologue: tile 0 -> stage 0
    {
#pragma unroll
        for (int p = 0; p < 4; p++) {
            int idx = tid + p * 256;
            int r = idx >> 4, sg = idx & 15;
            uint32_t off = (uint32_t)(r * KVLD + sg * 8) * 2u;
            cpa16(smem_u32(smh) + off, Kp + (size_t)r * HDIM + sg * 8);
            cpa16(smem_u32(smh) + (uint32_t)STG_H * 2u + off,
                  Vp + (size_t)r * HDIM + sg * 8);
        }
        cpa_commit();
    }

    for (int t = 0; t < ntiles; t++) {
        const int s = t & 1;
        const uint32_t stBase = smem_u32(smh) + (uint32_t)(s * 2 * STG_H) * 2u;
        cpa_wait<0>();
        __syncthreads();
        // prefetch tile t+1 into other stage
        if (t + 1 < ntiles) {
            const uint32_t nb = smem_u32(smh) + (uint32_t)(((t + 1) & 1) * 2 * STG_H) * 2u;
            const size_t g0 = (size_t)(t + 1) * 64;
#pragma unroll
            for (int p = 0; p < 4; p++) {
                int idx = tid + p * 256;
                int r = idx >> 4, sg = idx & 15;
                uint32_t off = (uint32_t)(r * KVLD + sg * 8) * 2u;
                cpa16(nb + off, Kp + (g0 + r) * HDIM + sg * 8);
                cpa16(nb + (uint32_t)STG_H * 2u + off, Vp + (g0 + r) * HDIM + sg * 8);
            }
            cpa_commit();
        }

        const int s0 = t * 64;
        // S = Q K^T (per warp: 16 rows x 64 cols)
        const uint32_t kBase = stBase +
            (uint32_t)(((lane >> 4) * 8 + (lane & 7)) * KVLD + ((lane >> 3) & 1) * 8) * 2u;
        float sa[8][4];
#pragma unroll
        for (int nt = 0; nt < 8; nt++)
#pragma unroll
            for (int e = 0; e < 4; e++) sa[nt][e] = 0.0f;
#pragma unroll
        for (int kb = 0; kb < 8; kb++) {
#pragma unroll
            for (int g = 0; g < 4; g++) {
                uint32_t bf[4];
                ldm4(bf, kBase + (uint32_t)(g * 16 * KVLD * 2) + (uint32_t)kb * 32u);
                mma_f16(sa[2 * g + 0], qf[kb], bf + 0);
                mma_f16(sa[2 * g + 1], qf[kb], bf + 2);
            }
        }

        // softcap: odd tanh poly (exact to 5e-6 for |s|<=29; in-distribution
        // |s| <~ 6) + clamp to the +-50 asymptote for safety. FMA pipe only.
        float tm0 = -1e30f, tm1 = -1e30f;
#pragma unroll
        for (int nt = 0; nt < 8; nt++) {
            int c = s0 + nt * 8 + lc;
#pragma unroll
            for (int e = 0; e < 4; e++) {
                float x = sa[nt][e];
                float u = (x * 0.02f) * (x * 0.02f);
                float pl = fmaf(u, -0.00886324f, 0.02186949f);
                pl = fmaf(u, pl, -0.05396825f);
                pl = fmaf(u, pl, 0.13333333f);
                pl = fmaf(u, pl, -0.33333333f);
                pl = fmaf(u, pl, 1.0f);
                sa[nt][e] = fminf(fmaxf(x * pl, -50.0f), 50.0f);
            }
            tm0 = fmaxf(tm0, fmaxf(c <= gr0 ? sa[nt][0] : -1e30f,
                                   c + 1 <= gr0 ? sa[nt][1] : -1e30f));
            tm1 = fmaxf(tm1, fmaxf(c <= gr1 ? sa[nt][2] : -1e30f,
                                   c + 1 <= gr1 ? sa[nt][3] : -1e30f));
        }
        tm0 = fmaxf(tm0, __shfl_xor_sync(0xffffffffu, tm0, 1));
        tm0 = fmaxf(tm0, __shfl_xor_sync(0xffffffffu, tm0, 2));
        tm1 = fmaxf(tm1, __shfl_xor_sync(0xffffffffu, tm1, 1));
        tm1 = fmaxf(tm1, __shfl_xor_sync(0xffffffffu, tm1, 2));
        float mn0 = fmaxf(m0, tm0), mn1 = fmaxf(m1, tm1);
        // rescale only when the running max changed (warp-uniform; exact skip)
        if (__any_sync(0xffffffffu, (mn0 > m0) || (mn1 > m1))) {
            float a0 = ex2f((m0 - mn0) * L2E);
            float a1 = ex2f((m1 - mn1) * L2E);
            m0 = mn0; m1 = mn1;
            ls0 *= a0; ls1 *= a1;
#pragma unroll
            for (int nt = 0; nt < 16; nt++) {
                o[nt][0] *= a0; o[nt][1] *= a0;
                o[nt][2] *= a1; o[nt][3] *= a1;
            }
        }
        // exp via MUFU ex2: p = 2^(s*log2e - m*log2e); masked -> t=-200 -> 0
        const float sh0 = -m0 * L2E, sh1 = -m1 * L2E;
        __half* pr0 = Ps + (wm + lr) * PLD + lc;
        __half* pr1 = pr0 + 8 * PLD;
#pragma unroll
        for (int nt = 0; nt < 8; nt++) {
            int c = s0 + nt * 8 + lc;
            float t0 = (c <= gr0) ? fmaf(sa[nt][0], L2E, sh0) : -200.0f;
            float t1 = (c + 1 <= gr0) ? fmaf(sa[nt][1], L2E, sh0) : -200.0f;
            float t2 = (c <= gr1) ? fmaf(sa[nt][2], L2E, sh1) : -200.0f;
            float t3 = (c + 1 <= gr1) ? fmaf(sa[nt][3], L2E, sh1) : -200.0f;
            float p0 = ex2f(t0), p1 = ex2f(t1);
            float p2 = ex2f(t2), p3 = ex2f(t3);
            ls0 += p0 + p1;
            ls1 += p2 + p3;
            *(__half2*)(pr0 + nt * 8) = __floats2half2_rn(p0, p1);
            *(__half2*)(pr1 + nt * 8) = __floats2half2_rn(p2, p3);
        }
        __syncwarp();  // P rows are warp-private: warp-level visibility only

        // O += P V (per warp: 16 rows x 128 cols)
        const uint32_t vBase = stBase + (uint32_t)STG_H * 2u +
            (uint32_t)((lane & 15) * KVLD + (lane >> 4) * 8) * 2u;
#pragma unroll
        for (int kb = 0; kb < 4; kb++) {
            uint32_t pf[4];
            ldm4(pf, pBase + (uint32_t)kb * 32u);
            const uint32_t vSt = vBase + (uint32_t)(kb * 16 * KVLD * 2);
#pragma unroll
            for (int j = 0; j < 8; j++) {
                uint32_t vf[4];
                ldm4t(vf, vSt + (uint32_t)(j * 16) * 2u);
                mma_f16(o[2 * j + 0], pf, vf + 0);
                mma_f16(o[2 * j + 1], pf, vf + 2);
            }
        }
        __syncthreads();  // all warps done reading stage s before overwrite
    }

    // finalize
    ls0 += __shfl_xor_sync(0xffffffffu, ls0, 1);
    ls0 += __shfl_xor_sync(0xffffffffu, ls0, 2);
    ls1 += __shfl_xor_sync(0xffffffffu, ls1, 1);
    ls1 += __shfl_xor_sync(0xffffffffu, ls1, 2);
    float i0 = 1.0f / ls0, i1 = 1.0f / ls1;
    __half* er0 = g_ench + ((size_t)(b * TT + gr0)) * 2048 + n * HDIM + lc;
    __half* er1 = g_ench + ((size_t)(b * TT + gr1)) * 2048 + n * HDIM + lc;
#pragma unroll
    for (int nt = 0; nt < 16; nt++) {
        *(__half2*)(er0 + nt * 8) = __floats2half2_rn(o[nt][0] * i0, o[nt][1] * i0);
        *(__half2*)(er1 + nt * 8) = __floats2half2_rn(o[nt][2] * i1, o[nt][3] * i1);
    }
}

// ---------------------------------------------------------------------------
extern "C" void kernel_launch(void* const* d_in, const int* in_sizes, int n_in,
                              void* d_out, int out_size)
{
    const float* x = (const float*)d_in[0];
    const int* positions = (const int*)d_in[1];
    // d_in[2] = attn_mask (causal) — analytic
    const float* w_q = (const float*)d_in[3];
    const float* w_kv = (const float*)d_in[4];
    const float* w_out = (const float*)d_in[5];
    float* out = (float*)d_out;

    float *qf, *kf;
    __half *xh, *wth, *woth, *ench, *qh, *kh;
    cudaGetSymbolAddress((void**)&qf, g_qf);
    cudaGetSymbolAddress((void**)&kf, g_kf);
    cudaGetSymbolAddress((void**)&qh, g_qh);
    cudaGetSymbolAddress((void**)&kh, g_kh);
    cudaGetSymbolAddress((void**)&xh, g_xh);
    cudaGetSymbolAddress((void**)&wth, g_wth);
    cudaGetSymbolAddress((void**)&woth, g_woth);
    cudaGetSymbolAddress((void**)&ench, g_ench);

    TsTab tt;
    for (int i = 0; i < 64; i++) tt.ts[i] = pow(10000.0, -(double)i / 64.0);

    // prep
    conv_half<<<(BB * TT * DD) / 1024, 256>>>(x, xh);
    transpose_half<<<dim3(4, 64, 16), dim3(32, 8)>>>(w_q, wth, 2048, 128);
    transpose_half<<<dim3(4, 64, 16), dim3(32, 8)>>>(
        w_kv, wth + (size_t)2048 * 2048, 2048, 128);
    transpose_half<<<dim3(64, 64, 1), dim3(32, 8)>>>(w_out, woth, 2048, 2048);
    rope_table<<<(BB * TT * 64) / 256, 256>>>(positions, tt);

    // merged QKV projection
    cudaFuncSetAttribute(gemm_h<0>, cudaFuncAttributeMaxDynamicSharedMemorySize,
                         HSMEM);
    cudaFuncSetAttribute(gemm_h<1>, cudaFuncAttributeMaxDynamicSharedMemorySize,
                         HSMEM);
    gemm_h<0><<<dim3(32, 32), 256, HSMEM>>>(xh, wth, nullptr);

    // fused rope + fp16 conversion
    rope_to_half<<<(BB * NHEADS * TT * 64) / 256, 256>>>(
        qf, qh, NHEADS, 0.08838834764831845f);
    rope_to_half<<<(BB * NKVH * TT * 64) / 256, 256>>>(kf, kh, NKVH, 1.0f);

    cudaFuncSetAttribute(attn_kernel, cudaFuncAttributeMaxDynamicSharedMemorySize,
                         SMEM_ATTN);
    attn_kernel<<<dim3(TT / 128, NHEADS, BB), 256, SMEM_ATTN>>>();

    // output projection
    gemm_h<1><<<dim3(16, 32), 256, HSMEM>>>(ench, woth, out);
}